// round 5
// baseline (speedup 1.0000x reference)
#include <cuda_runtime.h>
#include <cuda_bf16.h>

#define NN 50000
#define EE 600000
#define DD 128
#define KK 8
#define BB 64
#define ED 16

// Scratch (device globals are allowed; no runtime alloc)
__device__ float g_h[NN * DD];          // (1+eps)*x + agg
__device__ float g_xres[NN * DD];       // MLP output
__device__ float g_psum[BB * KK * DD];  // pocket sums
__device__ float g_pcnt[BB * KK];       // pocket counts
__device__ float g_pemb[BB * KK * DD];  // pocket embeddings

// ---------------------------------------------------------------------------
// Kernel 0: g_h = (1+eps)*x ; zero pocket accumulators
// ---------------------------------------------------------------------------
__global__ void init_kernel(const float* __restrict__ x, const float* __restrict__ epsp) {
    const float c = 1.0f + epsp[0];
    int tid = blockIdx.x * blockDim.x + threadIdx.x;
    int stride = gridDim.x * blockDim.x;
    const float4* x4 = (const float4*)x;
    float4* h4 = (float4*)g_h;
    for (int i = tid; i < NN * DD / 4; i += stride) {
        float4 v = x4[i];
        v.x *= c; v.y *= c; v.z *= c; v.w *= c;
        h4[i] = v;
    }
    for (int i = tid; i < BB * KK * DD; i += stride) g_psum[i] = 0.f;
    for (int i = tid; i < BB * KK; i += stride) g_pcnt[i] = 0.f;
}

// ---------------------------------------------------------------------------
// Kernel 1: edges. warp per edge: emb = ea@We+be ; msg = relu(x[src]+emb);
// red.add.v4 into g_h[dst].
// ---------------------------------------------------------------------------
__global__ void edge_kernel(const float* __restrict__ x,
                            const int* __restrict__ ei,
                            const float* __restrict__ ea,
                            const float* __restrict__ We,
                            const float* __restrict__ be) {
    __shared__ float sWe[ED * DD];
    __shared__ float sbe[DD];
    for (int i = threadIdx.x; i < ED * DD / 4; i += blockDim.x)
        ((float4*)sWe)[i] = ((const float4*)We)[i];
    if (threadIdx.x < DD) sbe[threadIdx.x] = be[threadIdx.x];
    __syncthreads();

    const int lane = threadIdx.x & 31;
    const int warp = blockIdx.x * (blockDim.x >> 5) + (threadIdx.x >> 5);
    const int nwarps = gridDim.x * (blockDim.x >> 5);
    const int* __restrict__ srcp = ei;
    const int* __restrict__ dstp = ei + EE;
    const int c0 = lane * 4;

    for (int e = warp; e < EE; e += nwarps) {
        float a = (lane < ED) ? __ldg(&ea[(size_t)e * ED + lane]) : 0.f;
        int s = srcp[e];
        int d = dstp[e];
        float4 acc = *(const float4*)(&sbe[c0]);
#pragma unroll
        for (int j = 0; j < ED; j++) {
            float aj = __shfl_sync(0xffffffffu, a, j);
            float4 w = *(const float4*)(&sWe[j * DD + c0]);
            acc.x += aj * w.x; acc.y += aj * w.y;
            acc.z += aj * w.z; acc.w += aj * w.w;
        }
        float4 xv = __ldg((const float4*)(x + (size_t)s * DD + c0));
        float mx = fmaxf(acc.x + xv.x, 0.f);
        float my = fmaxf(acc.y + xv.y, 0.f);
        float mz = fmaxf(acc.z + xv.z, 0.f);
        float mw = fmaxf(acc.w + xv.w, 0.f);
        float* p = g_h + (size_t)d * DD + c0;
        asm volatile("red.global.add.v4.f32 [%0], {%1, %2, %3, %4};"
                     :: "l"(p), "f"(mx), "f"(my), "f"(mz), "f"(mw) : "memory");
    }
}

// ---------------------------------------------------------------------------
// Kernel 2: node MLP: x_res = relu(h@W1+b1)@W2+b2. 64-row tile per block,
// W1+W2 resident in dynamic SMEM (192KB).
// ---------------------------------------------------------------------------
#define TM 64
__global__ void mlp_kernel(const float* __restrict__ W1, const float* __restrict__ b1,
                           const float* __restrict__ W2, const float* __restrict__ b2) {
    extern __shared__ float sm[];
    float* sW1 = sm;                 // 16384 floats
    float* sW2 = sm + 16384;         // 16384 floats
    float* sA  = sm + 32768;         // 8192 floats (64x128)
    float* sB  = sm + 40960;         // 8192 floats (64x128)
    const int tid = threadIdx.x;

    for (int i = tid; i < 16384 / 4; i += 256) {
        ((float4*)sW1)[i] = ((const float4*)W1)[i];
        ((float4*)sW2)[i] = ((const float4*)W2)[i];
    }
    const int row0 = blockIdx.x * TM;
    for (int i = tid; i < TM * DD / 4; i += 256) {
        int r = i >> 5;        // row within tile (32 float4 per row)
        int c = i & 31;
        float4 v = make_float4(0.f, 0.f, 0.f, 0.f);
        if (row0 + r < NN) v = ((const float4*)(g_h + (size_t)(row0 + r) * DD))[c];
        ((float4*)sA)[i] = v;
    }
    __syncthreads();

    const int warp = tid >> 5, lane = tid & 31;
    const int r0 = warp * 8;
    const int c0 = lane * 4;

    // GEMM1 + ReLU -> sB
    {
        float4 bb = *(const float4*)(b1 + c0);
        float4 acc[8];
#pragma unroll
        for (int i = 0; i < 8; i++) acc[i] = bb;
#pragma unroll 4
        for (int kk = 0; kk < DD; kk++) {
            float4 w = *(const float4*)(sW1 + kk * DD + c0);
#pragma unroll
            for (int i = 0; i < 8; i++) {
                float a = sA[(r0 + i) * DD + kk];
                acc[i].x += a * w.x; acc[i].y += a * w.y;
                acc[i].z += a * w.z; acc[i].w += a * w.w;
            }
        }
#pragma unroll
        for (int i = 0; i < 8; i++) {
            float4 v = acc[i];
            v.x = fmaxf(v.x, 0.f); v.y = fmaxf(v.y, 0.f);
            v.z = fmaxf(v.z, 0.f); v.w = fmaxf(v.w, 0.f);
            *(float4*)(sB + (r0 + i) * DD + c0) = v;
        }
    }
    __syncthreads();

    // GEMM2 -> g_xres
    {
        float4 bb = *(const float4*)(b2 + c0);
        float4 acc[8];
#pragma unroll
        for (int i = 0; i < 8; i++) acc[i] = bb;
#pragma unroll 4
        for (int kk = 0; kk < DD; kk++) {
            float4 w = *(const float4*)(sW2 + kk * DD + c0);
#pragma unroll
            for (int i = 0; i < 8; i++) {
                float a = sB[(r0 + i) * DD + kk];
                acc[i].x += a * w.x; acc[i].y += a * w.y;
                acc[i].z += a * w.z; acc[i].w += a * w.w;
            }
        }
#pragma unroll
        for (int i = 0; i < 8; i++) {
            int r = row0 + r0 + i;
            if (r < NN) *(float4*)(g_xres + (size_t)r * DD + c0) = acc[i];
        }
    }
}

// ---------------------------------------------------------------------------
// Kernel 3: pocket pooling. batch is sorted; warp owns a contiguous node
// range with SMEM [K][D] accumulator, flushes via atomics at graph changes.
// ---------------------------------------------------------------------------
__device__ __forceinline__ void pool_flush(float* acc, int curg, float& cnt, int lane) {
    if (curg < 0) return;
    float* base = g_psum + (size_t)curg * KK * DD;
    for (int i = lane; i < KK * DD; i += 32) {
        float v = acc[i];
        if (v != 0.f) atomicAdd(base + i, v);
        acc[i] = 0.f;
    }
    if (lane < KK && cnt != 0.f) atomicAdd(&g_pcnt[curg * KK + lane], cnt);
    cnt = 0.f;
}

__global__ void pool_kernel(const float* __restrict__ mask, const int* __restrict__ batch) {
    __shared__ float sacc[8][KK * DD];   // 8 warps/block * 4KB
    const int wib = threadIdx.x >> 5;
    const int lane = threadIdx.x & 31;
    const int gw = blockIdx.x * (blockDim.x >> 5) + wib;
    const int totalWarps = gridDim.x * (blockDim.x >> 5);
    float* acc = sacc[wib];

    for (int i = lane; i < KK * DD; i += 32) acc[i] = 0.f;
    __syncwarp();

    const int chunk = (NN + totalWarps - 1) / totalWarps;
    const int nstart = gw * chunk;
    const int nend = min(NN, nstart + chunk);

    float cnt = 0.f;
    int curg = -1;
    for (int n = nstart; n < nend; n++) {
        int g = batch[n];
        if (g != curg) {
            pool_flush(acc, curg, cnt, lane);
            curg = g;
        }
        float m = (lane < KK) ? mask[(size_t)n * KK + lane] : 0.f;
        float4 xv = *(const float4*)(g_xres + (size_t)n * DD + lane * 4);
#pragma unroll
        for (int k = 0; k < KK; k++) {
            float mk = __shfl_sync(0xffffffffu, m, k);
            if (mk != 0.f) {
                float4* a = (float4*)(acc + k * DD + lane * 4);
                float4 v = *a;
                v.x += xv.x; v.y += xv.y; v.z += xv.z; v.w += xv.w;
                *a = v;
            }
        }
        cnt += m;
    }
    pool_flush(acc, curg, cnt, lane);
}

// ---------------------------------------------------------------------------
// Kernel 4: pocket_emb = (psum/(cnt+1e-9)) @ Wv + bv. Warp per row (512 rows).
// ---------------------------------------------------------------------------
__global__ void pemb_kernel(const float* __restrict__ Wv, const float* __restrict__ bv) {
    const int lane = threadIdx.x & 31;
    const int r = blockIdx.x * (blockDim.x >> 5) + (threadIdx.x >> 5);
    if (r >= BB * KK) return;
    const float rinv = 1.f / (g_pcnt[r] + 1e-9f);
    const int c0 = lane * 4;
    float4 acc = *(const float4*)(bv + c0);
#pragma unroll 8
    for (int d = 0; d < DD; d++) {
        float a = g_psum[r * DD + d] * rinv;
        float4 w = __ldg((const float4*)(Wv + d * DD + c0));
        acc.x += a * w.x; acc.y += a * w.y; acc.z += a * w.z; acc.w += a * w.w;
    }
    *(float4*)(g_pemb + r * DD + c0) = acc;
}

// ---------------------------------------------------------------------------
// Kernel 5: residual pocket feedback + LayerNorm + ReLU. Warp per node.
// ---------------------------------------------------------------------------
__global__ void final_kernel(const float* __restrict__ mask, const int* __restrict__ batch,
                             const float* __restrict__ gamma, const float* __restrict__ beta,
                             float* __restrict__ out) {
    const int lane = threadIdx.x & 31;
    const int gw = blockIdx.x * (blockDim.x >> 5) + (threadIdx.x >> 5);
    const int tw = gridDim.x * (blockDim.x >> 5);
    const int c0 = lane * 4;
    const float4 gm = *(const float4*)(gamma + c0);
    const float4 bt = *(const float4*)(beta + c0);

    for (int n = gw; n < NN; n += tw) {
        int g = batch[n];
        float m = (lane < KK) ? mask[(size_t)n * KK + lane] : 0.f;
        float4 v = *(const float4*)(g_xres + (size_t)n * DD + c0);
        const float* pe = g_pemb + (size_t)g * KK * DD;
#pragma unroll
        for (int k = 0; k < KK; k++) {
            float mk = __shfl_sync(0xffffffffu, m, k);
            if (mk != 0.f) {
                float4 p = __ldg((const float4*)(pe + k * DD + c0));
                v.x += p.x; v.y += p.y; v.z += p.z; v.w += p.w;
            }
        }
        // two-pass LayerNorm over 128 dims (warp-held)
        float s = v.x + v.y + v.z + v.w;
#pragma unroll
        for (int off = 16; off; off >>= 1) s += __shfl_xor_sync(0xffffffffu, s, off);
        float mu = s * (1.f / 128.f);
        float dx = v.x - mu, dy = v.y - mu, dz = v.z - mu, dw = v.w - mu;
        float sq = dx * dx + dy * dy + dz * dz + dw * dw;
#pragma unroll
        for (int off = 16; off; off >>= 1) sq += __shfl_xor_sync(0xffffffffu, sq, off);
        float rstd = rsqrtf(sq * (1.f / 128.f) + 1e-5f);
        float4 y;
        y.x = fmaxf(dx * rstd * gm.x + bt.x, 0.f);
        y.y = fmaxf(dy * rstd * gm.y + bt.y, 0.f);
        y.z = fmaxf(dz * rstd * gm.z + bt.z, 0.f);
        y.w = fmaxf(dw * rstd * gm.w + bt.w, 0.f);
        *(float4*)(out + (size_t)n * DD + c0) = y;
    }
}

// ---------------------------------------------------------------------------
extern "C" void kernel_launch(void* const* d_in, const int* in_sizes, int n_in,
                              void* d_out, int out_size) {
    const float* x     = (const float*)d_in[0];
    const int*   ei    = (const int*)d_in[1];
    const float* ea    = (const float*)d_in[2];
    const float* pmask = (const float*)d_in[3];
    const int*   batch = (const int*)d_in[4];
    const float* We    = (const float*)d_in[5];
    const float* be    = (const float*)d_in[6];
    const float* W1    = (const float*)d_in[7];
    const float* b1    = (const float*)d_in[8];
    const float* W2    = (const float*)d_in[9];
    const float* b2    = (const float*)d_in[10];
    const float* eps   = (const float*)d_in[11];
    const float* gamma = (const float*)d_in[12];
    const float* beta  = (const float*)d_in[13];
    const float* Wv    = (const float*)d_in[14];
    const float* bv    = (const float*)d_in[15];
    float* out = (float*)d_out;

    static_assert(TM * DD * 2 * 4 + 2 * DD * DD * 4 == 196608, "smem layout");
    cudaFuncSetAttribute(mlp_kernel, cudaFuncAttributeMaxDynamicSharedMemorySize, 196608);

    init_kernel<<<4096, 256>>>(x, eps);
    edge_kernel<<<4096, 256>>>(x, ei, ea, We, be);
    mlp_kernel<<<(NN + TM - 1) / TM, 256, 196608>>>(W1, b1, W2, b2);
    pool_kernel<<<64, 256>>>(pmask, batch);
    pemb_kernel<<<(BB * KK + 7) / 8, 256>>>(Wv, bv);
    final_kernel<<<2048, 256>>>(pmask, batch, gamma, beta, out);
}

// round 6
// speedup vs baseline: 1.1537x; 1.1537x over previous
#include <cuda_runtime.h>
#include <cuda_bf16.h>

#define NN 50000
#define EE 600000
#define DD 128
#define KK 8
#define BB 64
#define ED 16
#define PS 8   // slices per graph for pooling

// Scratch (device globals; no runtime alloc)
__device__ float g_h[NN * DD];            // (1+eps)*x + agg
__device__ float g_xres[NN * DD];         // MLP output
__device__ float g_psum[BB * KK * DD];    // pocket sums
__device__ float g_pcnt[BB * KK];         // pocket counts
__device__ float g_pemb[BB * KK * DD];    // pocket embeddings
__device__ int   g_gstart[BB + 1];        // graph start offsets (batch sorted)
__device__ float g_part[BB * PS * KK * DD];   // pooling partials (atomic-free)
__device__ float g_cntpart[BB * PS * KK];

// packed-fp32 helpers (FFMA2: exact fp32 math, 2x fma-pipe throughput)
#define FMA2(acc, a2, w2) \
    asm("fma.rn.f32x2 %0, %1, %2, %0;" : "+l"(acc) : "l"(a2), "l"(w2))
#define DUP2(a2, f) \
    asm("mov.b64 %0, {%1, %1};" : "=l"(a2) : "f"(f))
#define PACK2(p, lo, hi) \
    asm("mov.b64 %0, {%1, %2};" : "=l"(p) : "f"(lo), "f"(hi))
#define UNPACK2(lo, hi, p) \
    asm("mov.b64 {%0, %1}, %2;" : "=f"(lo), "=f"(hi) : "l"(p))

// ---------------------------------------------------------------------------
// Kernel 0: g_h = (1+eps)*x
// ---------------------------------------------------------------------------
__global__ void init_kernel(const float* __restrict__ x, const float* __restrict__ epsp) {
    const float c = 1.0f + epsp[0];
    int tid = blockIdx.x * blockDim.x + threadIdx.x;
    int stride = gridDim.x * blockDim.x;
    const float4* x4 = (const float4*)x;
    float4* h4 = (float4*)g_h;
    for (int i = tid; i < NN * DD / 4; i += stride) {
        float4 v = x4[i];
        v.x *= c; v.y *= c; v.z *= c; v.w *= c;
        h4[i] = v;
    }
}

// ---------------------------------------------------------------------------
// Kernel 0b: graph boundary offsets from sorted batch
// ---------------------------------------------------------------------------
__global__ void bounds_kernel(const int* __restrict__ batch) {
    int n = blockIdx.x * blockDim.x + threadIdx.x;
    if (n >= NN) return;
    int b1 = batch[n];
    int b0 = (n == 0) ? -1 : batch[n - 1];
    for (int g = b0 + 1; g <= b1; g++) g_gstart[g] = n;
    if (n == NN - 1)
        for (int g = b1 + 1; g <= BB; g++) g_gstart[g] = NN;
}

// ---------------------------------------------------------------------------
// Kernel 1: edges. warp per edge; emb = ea@We+be via FFMA2;
// msg = relu(x[src]+emb); red.add.v4 into g_h[dst].
// ---------------------------------------------------------------------------
__global__ void edge_kernel(const float* __restrict__ x,
                            const int* __restrict__ ei,
                            const float* __restrict__ ea,
                            const float* __restrict__ We,
                            const float* __restrict__ be) {
    __shared__ float sWe[ED * DD];
    __shared__ float sbe[DD];
    for (int i = threadIdx.x; i < ED * DD / 4; i += blockDim.x)
        ((float4*)sWe)[i] = ((const float4*)We)[i];
    if (threadIdx.x < DD) sbe[threadIdx.x] = be[threadIdx.x];
    __syncthreads();

    const int lane = threadIdx.x & 31;
    const int warp = blockIdx.x * (blockDim.x >> 5) + (threadIdx.x >> 5);
    const int nwarps = gridDim.x * (blockDim.x >> 5);
    const int* __restrict__ srcp = ei;
    const int* __restrict__ dstp = ei + EE;
    const int c0 = lane * 4;

    for (int e = warp; e < EE; e += nwarps) {
        float a = (lane < ED) ? __ldg(&ea[(size_t)e * ED + lane]) : 0.f;
        int s = srcp[e];
        int d = dstp[e];
        float4 bbv = *(const float4*)(&sbe[c0]);
        unsigned long long acc0, acc1;
        PACK2(acc0, bbv.x, bbv.y);
        PACK2(acc1, bbv.z, bbv.w);
#pragma unroll
        for (int j = 0; j < ED; j++) {
            float aj = __shfl_sync(0xffffffffu, a, j);
            unsigned long long a2;
            DUP2(a2, aj);
            ulonglong2 w = *(const ulonglong2*)(&sWe[j * DD + c0]);
            FMA2(acc0, a2, w.x);
            FMA2(acc1, a2, w.y);
        }
        float ex, ey, ez, ew;
        UNPACK2(ex, ey, acc0);
        UNPACK2(ez, ew, acc1);
        float4 xv = __ldg((const float4*)(x + (size_t)s * DD + c0));
        float mx = fmaxf(ex + xv.x, 0.f);
        float my = fmaxf(ey + xv.y, 0.f);
        float mz = fmaxf(ez + xv.z, 0.f);
        float mw = fmaxf(ew + xv.w, 0.f);
        float* p = g_h + (size_t)d * DD + c0;
        asm volatile("red.global.add.v4.f32 [%0], {%1, %2, %3, %4};"
                     :: "l"(p), "f"(mx), "f"(my), "f"(mz), "f"(mw) : "memory");
    }
}

// ---------------------------------------------------------------------------
// Kernel 2: node MLP: x_res = relu(h@W1+b1)@W2+b2, FFMA2 inner loop.
// ---------------------------------------------------------------------------
#define TM 64
__device__ __forceinline__ void gemm_tile_f32x2(const float* __restrict__ sW,
                                                const float* __restrict__ sIn,
                                                const float* __restrict__ bias,
                                                int r0, int c0, float4 out[8]) {
    unsigned long long acc[8][2];
    {
        float4 bb = *(const float4*)(bias + c0);
        unsigned long long blo, bhi;
        PACK2(blo, bb.x, bb.y);
        PACK2(bhi, bb.z, bb.w);
#pragma unroll
        for (int i = 0; i < 8; i++) { acc[i][0] = blo; acc[i][1] = bhi; }
    }
#pragma unroll 2
    for (int kk = 0; kk < DD; kk += 4) {
        ulonglong2 w0 = *(const ulonglong2*)(sW + (kk + 0) * DD + c0);
        ulonglong2 w1 = *(const ulonglong2*)(sW + (kk + 1) * DD + c0);
        ulonglong2 w2 = *(const ulonglong2*)(sW + (kk + 2) * DD + c0);
        ulonglong2 w3 = *(const ulonglong2*)(sW + (kk + 3) * DD + c0);
#pragma unroll
        for (int i = 0; i < 8; i++) {
            float4 av = *(const float4*)(sIn + (r0 + i) * DD + kk);
            unsigned long long a2;
            DUP2(a2, av.x); FMA2(acc[i][0], a2, w0.x); FMA2(acc[i][1], a2, w0.y);
            DUP2(a2, av.y); FMA2(acc[i][0], a2, w1.x); FMA2(acc[i][1], a2, w1.y);
            DUP2(a2, av.z); FMA2(acc[i][0], a2, w2.x); FMA2(acc[i][1], a2, w2.y);
            DUP2(a2, av.w); FMA2(acc[i][0], a2, w3.x); FMA2(acc[i][1], a2, w3.y);
        }
    }
#pragma unroll
    for (int i = 0; i < 8; i++) {
        float4 v;
        UNPACK2(v.x, v.y, acc[i][0]);
        UNPACK2(v.z, v.w, acc[i][1]);
        out[i] = v;
    }
}

__global__ void mlp_kernel(const float* __restrict__ W1, const float* __restrict__ b1,
                           const float* __restrict__ W2, const float* __restrict__ b2) {
    extern __shared__ float sm[];
    float* sW1 = sm;                 // 16384 floats
    float* sW2 = sm + 16384;         // 16384 floats
    float* sA  = sm + 32768;         // 8192 floats (64x128)
    float* sB  = sm + 40960;         // 8192 floats (64x128)
    const int tid = threadIdx.x;

    for (int i = tid; i < 16384 / 4; i += 256) {
        ((float4*)sW1)[i] = ((const float4*)W1)[i];
        ((float4*)sW2)[i] = ((const float4*)W2)[i];
    }
    const int row0 = blockIdx.x * TM;
    for (int i = tid; i < TM * DD / 4; i += 256) {
        int r = i >> 5;
        int c = i & 31;
        float4 v = make_float4(0.f, 0.f, 0.f, 0.f);
        if (row0 + r < NN) v = ((const float4*)(g_h + (size_t)(row0 + r) * DD))[c];
        ((float4*)sA)[i] = v;
    }
    __syncthreads();

    const int warp = tid >> 5, lane = tid & 31;
    const int r0 = warp * 8;
    const int c0 = lane * 4;

    float4 res[8];
    gemm_tile_f32x2(sW1, sA, b1, r0, c0, res);
#pragma unroll
    for (int i = 0; i < 8; i++) {
        float4 v = res[i];
        v.x = fmaxf(v.x, 0.f); v.y = fmaxf(v.y, 0.f);
        v.z = fmaxf(v.z, 0.f); v.w = fmaxf(v.w, 0.f);
        *(float4*)(sB + (r0 + i) * DD + c0) = v;
    }
    __syncthreads();

    gemm_tile_f32x2(sW2, sB, b2, r0, c0, res);
#pragma unroll
    for (int i = 0; i < 8; i++) {
        int r = row0 + r0 + i;
        if (r < NN) *(float4*)(g_xres + (size_t)r * DD + c0) = res[i];
    }
}

// ---------------------------------------------------------------------------
// Kernel 3: pocket pooling, atomic-free. Block = (graph b, slice s).
// Per-warp SMEM [K][D] accumulator, block-reduce, write partials.
// ---------------------------------------------------------------------------
__global__ void pool_kernel(const float* __restrict__ mask) {
    __shared__ float sacc[8][KK * DD];
    __shared__ float scnt[8][KK];
    const int b = blockIdx.x / PS;
    const int s = blockIdx.x % PS;
    const int gs = g_gstart[b];
    const int len = g_gstart[b + 1] - gs;
    const int start = gs + (len * s) / PS;
    const int end = gs + (len * (s + 1)) / PS;

    const int wib = threadIdx.x >> 5;
    const int lane = threadIdx.x & 31;
    float* acc = sacc[wib];
    for (int i = lane; i < KK * DD; i += 32) acc[i] = 0.f;
    float cnt = 0.f;

    for (int n = start + wib; n < end; n += 8) {
        float m = (lane < KK) ? mask[(size_t)n * KK + lane] : 0.f;
        float4 xv = *(const float4*)(g_xres + (size_t)n * DD + lane * 4);
#pragma unroll
        for (int k = 0; k < KK; k++) {
            float mk = __shfl_sync(0xffffffffu, m, k);
            if (mk != 0.f) {
                float4* a = (float4*)(acc + k * DD + lane * 4);
                float4 v = *a;
                v.x += xv.x; v.y += xv.y; v.z += xv.z; v.w += xv.w;
                *a = v;
            }
        }
        cnt += m;
    }
    if (lane < KK) scnt[wib][lane] = cnt;
    __syncthreads();

    float* outp = g_part + (size_t)blockIdx.x * KK * DD;
    for (int i = threadIdx.x; i < KK * DD; i += blockDim.x) {
        float v = 0.f;
#pragma unroll
        for (int w = 0; w < 8; w++) v += sacc[w][i];
        outp[i] = v;
    }
    if (threadIdx.x < KK) {
        float c = 0.f;
#pragma unroll
        for (int w = 0; w < 8; w++) c += scnt[w][threadIdx.x];
        g_cntpart[blockIdx.x * KK + threadIdx.x] = c;
    }
}

// ---------------------------------------------------------------------------
// Kernel 3b: reduce partials -> g_psum, g_pcnt
// ---------------------------------------------------------------------------
__global__ void reduce_kernel() {
    int tid = blockIdx.x * blockDim.x + threadIdx.x;
    int stride = gridDim.x * blockDim.x;
    for (int i = tid; i < BB * KK * DD; i += stride) {
        int b = i / (KK * DD);
        int j = i % (KK * DD);
        float v = 0.f;
#pragma unroll
        for (int s = 0; s < PS; s++) v += g_part[(size_t)(b * PS + s) * KK * DD + j];
        g_psum[i] = v;
    }
    for (int i = tid; i < BB * KK; i += stride) {
        int b = i / KK;
        int k = i % KK;
        float c = 0.f;
#pragma unroll
        for (int s = 0; s < PS; s++) c += g_cntpart[(b * PS + s) * KK + k];
        g_pcnt[i] = c;
    }
}

// ---------------------------------------------------------------------------
// Kernel 4: pocket_emb = (psum/(cnt+1e-9)) @ Wv + bv. Warp per row (512 rows).
// ---------------------------------------------------------------------------
__global__ void pemb_kernel(const float* __restrict__ Wv, const float* __restrict__ bv) {
    const int lane = threadIdx.x & 31;
    const int r = blockIdx.x * (blockDim.x >> 5) + (threadIdx.x >> 5);
    if (r >= BB * KK) return;
    const float rinv = 1.f / (g_pcnt[r] + 1e-9f);
    const int c0 = lane * 4;
    float4 acc = *(const float4*)(bv + c0);
#pragma unroll 8
    for (int d = 0; d < DD; d++) {
        float a = g_psum[r * DD + d] * rinv;
        float4 w = __ldg((const float4*)(Wv + d * DD + c0));
        acc.x += a * w.x; acc.y += a * w.y; acc.z += a * w.z; acc.w += a * w.w;
    }
    *(float4*)(g_pemb + r * DD + c0) = acc;
}

// ---------------------------------------------------------------------------
// Kernel 5: residual pocket feedback + LayerNorm + ReLU. Warp per node.
// ---------------------------------------------------------------------------
__global__ void final_kernel(const float* __restrict__ mask, const int* __restrict__ batch,
                             const float* __restrict__ gamma, const float* __restrict__ beta,
                             float* __restrict__ out) {
    const int lane = threadIdx.x & 31;
    const int gw = blockIdx.x * (blockDim.x >> 5) + (threadIdx.x >> 5);
    const int tw = gridDim.x * (blockDim.x >> 5);
    const int c0 = lane * 4;
    const float4 gm = *(const float4*)(gamma + c0);
    const float4 bt = *(const float4*)(beta + c0);

    for (int n = gw; n < NN; n += tw) {
        int g = batch[n];
        float m = (lane < KK) ? mask[(size_t)n * KK + lane] : 0.f;
        float4 v = *(const float4*)(g_xres + (size_t)n * DD + c0);
        const float* pe = g_pemb + (size_t)g * KK * DD;
#pragma unroll
        for (int k = 0; k < KK; k++) {
            float mk = __shfl_sync(0xffffffffu, m, k);
            if (mk != 0.f) {
                float4 p = __ldg((const float4*)(pe + k * DD + c0));
                v.x += p.x; v.y += p.y; v.z += p.z; v.w += p.w;
            }
        }
        float s = v.x + v.y + v.z + v.w;
#pragma unroll
        for (int off = 16; off; off >>= 1) s += __shfl_xor_sync(0xffffffffu, s, off);
        float mu = s * (1.f / 128.f);
        float dx = v.x - mu, dy = v.y - mu, dz = v.z - mu, dw = v.w - mu;
        float sq = dx * dx + dy * dy + dz * dz + dw * dw;
#pragma unroll
        for (int off = 16; off; off >>= 1) sq += __shfl_xor_sync(0xffffffffu, sq, off);
        float rstd = rsqrtf(sq * (1.f / 128.f) + 1e-5f);
        float4 y;
        y.x = fmaxf(dx * rstd * gm.x + bt.x, 0.f);
        y.y = fmaxf(dy * rstd * gm.y + bt.y, 0.f);
        y.z = fmaxf(dz * rstd * gm.z + bt.z, 0.f);
        y.w = fmaxf(dw * rstd * gm.w + bt.w, 0.f);
        *(float4*)(out + (size_t)n * DD + c0) = y;
    }
}

// ---------------------------------------------------------------------------
extern "C" void kernel_launch(void* const* d_in, const int* in_sizes, int n_in,
                              void* d_out, int out_size) {
    const float* x     = (const float*)d_in[0];
    const int*   ei    = (const int*)d_in[1];
    const float* ea    = (const float*)d_in[2];
    const float* pmask = (const float*)d_in[3];
    const int*   batch = (const int*)d_in[4];
    const float* We    = (const float*)d_in[5];
    const float* be    = (const float*)d_in[6];
    const float* W1    = (const float*)d_in[7];
    const float* b1    = (const float*)d_in[8];
    const float* W2    = (const float*)d_in[9];
    const float* b2    = (const float*)d_in[10];
    const float* eps   = (const float*)d_in[11];
    const float* gamma = (const float*)d_in[12];
    const float* beta  = (const float*)d_in[13];
    const float* Wv    = (const float*)d_in[14];
    const float* bv    = (const float*)d_in[15];
    float* out = (float*)d_out;

    static_assert(TM * DD * 2 * 4 + 2 * DD * DD * 4 == 196608, "smem layout");
    cudaFuncSetAttribute(mlp_kernel, cudaFuncAttributeMaxDynamicSharedMemorySize, 196608);

    init_kernel<<<2048, 256>>>(x, eps);
    bounds_kernel<<<(NN + 255) / 256, 256>>>(batch);
    edge_kernel<<<4096, 256>>>(x, ei, ea, We, be);
    mlp_kernel<<<(NN + TM - 1) / TM, 256, 196608>>>(W1, b1, W2, b2);
    pool_kernel<<<BB * PS, 256>>>(pmask);
    reduce_kernel<<<64, 256>>>();
    pemb_kernel<<<(BB * KK + 7) / 8, 256>>>(Wv, bv);
    final_kernel<<<2048, 256>>>(pmask, batch, gamma, beta, out);
}

// round 7
// speedup vs baseline: 1.1720x; 1.0159x over previous
#include <cuda_runtime.h>
#include <cuda_bf16.h>

#define NN 50000
#define EE 600000
#define DD 128
#define KK 8
#define BB 64
#define ED 16
#define PS 8   // slices per graph for pooling

// Scratch (device globals; no runtime alloc)
__device__ float g_h[NN * DD];            // (1+eps)*x + agg, then relu(h@W1+b1) in-place
__device__ float g_xres[NN * DD];         // MLP output
__device__ float g_psum[BB * KK * DD];    // pocket sums
__device__ float g_pcnt[BB * KK];         // pocket counts
__device__ float g_pemb[BB * KK * DD];    // pocket embeddings
__device__ int   g_gstart[BB + 1];        // graph start offsets (batch sorted)
__device__ float g_part[BB * PS * KK * DD];   // pooling partials (atomic-free)
__device__ float g_cntpart[BB * PS * KK];

// packed-fp32 helpers (FFMA2: exact fp32 math, 2x fma-pipe throughput)
#define FMA2(acc, a2, w2) \
    asm("fma.rn.f32x2 %0, %1, %2, %0;" : "+l"(acc) : "l"(a2), "l"(w2))
#define DUP2(a2, f) \
    asm("mov.b64 %0, {%1, %1};" : "=l"(a2) : "f"(f))
#define PACK2(p, lo, hi) \
    asm("mov.b64 %0, {%1, %2};" : "=l"(p) : "f"(lo), "f"(hi))
#define UNPACK2(lo, hi, p) \
    asm("mov.b64 {%0, %1}, %2;" : "=f"(lo), "=f"(hi) : "l"(p))

// ---------------------------------------------------------------------------
// Kernel 0: g_h = (1+eps)*x
// ---------------------------------------------------------------------------
__global__ void init_kernel(const float* __restrict__ x, const float* __restrict__ epsp) {
    const float c = 1.0f + epsp[0];
    int tid = blockIdx.x * blockDim.x + threadIdx.x;
    int stride = gridDim.x * blockDim.x;
    const float4* x4 = (const float4*)x;
    float4* h4 = (float4*)g_h;
    for (int i = tid; i < NN * DD / 4; i += stride) {
        float4 v = x4[i];
        v.x *= c; v.y *= c; v.z *= c; v.w *= c;
        h4[i] = v;
    }
}

// ---------------------------------------------------------------------------
// Kernel 0b: graph boundary offsets from sorted batch
// ---------------------------------------------------------------------------
__global__ void bounds_kernel(const int* __restrict__ batch) {
    int n = blockIdx.x * blockDim.x + threadIdx.x;
    if (n >= NN) return;
    int b1 = batch[n];
    int b0 = (n == 0) ? -1 : batch[n - 1];
    for (int g = b0 + 1; g <= b1; g++) g_gstart[g] = n;
    if (n == NN - 1)
        for (int g = b1 + 1; g <= BB; g++) g_gstart[g] = NN;
}

// ---------------------------------------------------------------------------
// Kernel 1: edges. warp per edge; emb = ea@We+be via FFMA2;
// msg = relu(x[src]+emb); red.add.v4 into g_h[dst].
// ---------------------------------------------------------------------------
__global__ void edge_kernel(const float* __restrict__ x,
                            const int* __restrict__ ei,
                            const float* __restrict__ ea,
                            const float* __restrict__ We,
                            const float* __restrict__ be) {
    __shared__ float sWe[ED * DD];
    __shared__ float sbe[DD];
    for (int i = threadIdx.x; i < ED * DD / 4; i += blockDim.x)
        ((float4*)sWe)[i] = ((const float4*)We)[i];
    if (threadIdx.x < DD) sbe[threadIdx.x] = be[threadIdx.x];
    __syncthreads();

    const int lane = threadIdx.x & 31;
    const int warp = blockIdx.x * (blockDim.x >> 5) + (threadIdx.x >> 5);
    const int nwarps = gridDim.x * (blockDim.x >> 5);
    const int* __restrict__ srcp = ei;
    const int* __restrict__ dstp = ei + EE;
    const int c0 = lane * 4;

    for (int e = warp; e < EE; e += nwarps) {
        float a = (lane < ED) ? __ldg(&ea[(size_t)e * ED + lane]) : 0.f;
        int s = srcp[e];
        int d = dstp[e];
        float4 bbv = *(const float4*)(&sbe[c0]);
        unsigned long long acc0, acc1;
        PACK2(acc0, bbv.x, bbv.y);
        PACK2(acc1, bbv.z, bbv.w);
#pragma unroll
        for (int j = 0; j < ED; j++) {
            float aj = __shfl_sync(0xffffffffu, a, j);
            unsigned long long a2;
            DUP2(a2, aj);
            ulonglong2 w = *(const ulonglong2*)(&sWe[j * DD + c0]);
            FMA2(acc0, a2, w.x);
            FMA2(acc1, a2, w.y);
        }
        float ex, ey, ez, ew;
        UNPACK2(ex, ey, acc0);
        UNPACK2(ez, ew, acc1);
        float4 xv = __ldg((const float4*)(x + (size_t)s * DD + c0));
        float mx = fmaxf(ex + xv.x, 0.f);
        float my = fmaxf(ey + xv.y, 0.f);
        float mz = fmaxf(ez + xv.z, 0.f);
        float mw = fmaxf(ew + xv.w, 0.f);
        float* p = g_h + (size_t)d * DD + c0;
        asm volatile("red.global.add.v4.f32 [%0], {%1, %2, %3, %4};"
                     :: "l"(p), "f"(mx), "f"(my), "f"(mz), "f"(mw) : "memory");
    }
}

// ---------------------------------------------------------------------------
// Kernel 2: node MLP split into two GEMM kernels, each 96KB smem so
// 2 blocks/SM (16 warps) instead of 1 (8 warps).
//   mlp1: g_h = relu(g_h@W1+b1)   (row-local -> in-place safe)
//   mlp2: g_xres = g_h@W2+b2
// ---------------------------------------------------------------------------
#define TM 64
__device__ __forceinline__ void gemm_tile_f32x2(const float* __restrict__ sW,
                                                const float* __restrict__ sIn,
                                                const float* __restrict__ bias,
                                                int r0, int c0, float4 out[8]) {
    unsigned long long acc[8][2];
    {
        float4 bb = *(const float4*)(bias + c0);
        unsigned long long blo, bhi;
        PACK2(blo, bb.x, bb.y);
        PACK2(bhi, bb.z, bb.w);
#pragma unroll
        for (int i = 0; i < 8; i++) { acc[i][0] = blo; acc[i][1] = bhi; }
    }
#pragma unroll 2
    for (int kk = 0; kk < DD; kk += 4) {
        ulonglong2 w0 = *(const ulonglong2*)(sW + (kk + 0) * DD + c0);
        ulonglong2 w1 = *(const ulonglong2*)(sW + (kk + 1) * DD + c0);
        ulonglong2 w2 = *(const ulonglong2*)(sW + (kk + 2) * DD + c0);
        ulonglong2 w3 = *(const ulonglong2*)(sW + (kk + 3) * DD + c0);
#pragma unroll
        for (int i = 0; i < 8; i++) {
            float4 av = *(const float4*)(sIn + (r0 + i) * DD + kk);
            unsigned long long a2;
            DUP2(a2, av.x); FMA2(acc[i][0], a2, w0.x); FMA2(acc[i][1], a2, w0.y);
            DUP2(a2, av.y); FMA2(acc[i][0], a2, w1.x); FMA2(acc[i][1], a2, w1.y);
            DUP2(a2, av.z); FMA2(acc[i][0], a2, w2.x); FMA2(acc[i][1], a2, w2.y);
            DUP2(a2, av.w); FMA2(acc[i][0], a2, w3.x); FMA2(acc[i][1], a2, w3.y);
        }
    }
#pragma unroll
    for (int i = 0; i < 8; i++) {
        float4 v;
        UNPACK2(v.x, v.y, acc[i][0]);
        UNPACK2(v.z, v.w, acc[i][1]);
        out[i] = v;
    }
}

template <bool RELU>
__device__ __forceinline__ void mlp_body(const float* __restrict__ W,
                                         const float* __restrict__ b,
                                         const float* __restrict__ in,
                                         float* __restrict__ outg) {
    extern __shared__ float sm[];
    float* sW = sm;                  // 16384 floats (64KB)
    float* sA = sm + 16384;          // 8192 floats (32KB)
    const int tid = threadIdx.x;

    for (int i = tid; i < 16384 / 4; i += 256)
        ((float4*)sW)[i] = ((const float4*)W)[i];
    const int row0 = blockIdx.x * TM;
    for (int i = tid; i < TM * DD / 4; i += 256) {
        int r = i >> 5;
        int c = i & 31;
        float4 v = make_float4(0.f, 0.f, 0.f, 0.f);
        if (row0 + r < NN) v = ((const float4*)(in + (size_t)(row0 + r) * DD))[c];
        ((float4*)sA)[i] = v;
    }
    __syncthreads();

    const int warp = tid >> 5, lane = tid & 31;
    const int r0 = warp * 8;
    const int c0 = lane * 4;

    float4 res[8];
    gemm_tile_f32x2(sW, sA, b, r0, c0, res);
#pragma unroll
    for (int i = 0; i < 8; i++) {
        int r = row0 + r0 + i;
        if (r < NN) {
            float4 v = res[i];
            if (RELU) {
                v.x = fmaxf(v.x, 0.f); v.y = fmaxf(v.y, 0.f);
                v.z = fmaxf(v.z, 0.f); v.w = fmaxf(v.w, 0.f);
            }
            *(float4*)(outg + (size_t)r * DD + c0) = v;
        }
    }
}

__global__ void __launch_bounds__(256, 2)
mlp1_kernel(const float* __restrict__ W1, const float* __restrict__ b1) {
    mlp_body<true>(W1, b1, g_h, g_h);
}

__global__ void __launch_bounds__(256, 2)
mlp2_kernel(const float* __restrict__ W2, const float* __restrict__ b2) {
    mlp_body<false>(W2, b2, g_h, g_xres);
}

// ---------------------------------------------------------------------------
// Kernel 3: pocket pooling, atomic-free. Block = (graph b, slice s).
// ---------------------------------------------------------------------------
__global__ void pool_kernel(const float* __restrict__ mask) {
    __shared__ float sacc[8][KK * DD];
    __shared__ float scnt[8][KK];
    const int b = blockIdx.x / PS;
    const int s = blockIdx.x % PS;
    const int gs = g_gstart[b];
    const int len = g_gstart[b + 1] - gs;
    const int start = gs + (len * s) / PS;
    const int end = gs + (len * (s + 1)) / PS;

    const int wib = threadIdx.x >> 5;
    const int lane = threadIdx.x & 31;
    float* acc = sacc[wib];
    for (int i = lane; i < KK * DD; i += 32) acc[i] = 0.f;
    float cnt = 0.f;

    for (int n = start + wib; n < end; n += 8) {
        float m = (lane < KK) ? mask[(size_t)n * KK + lane] : 0.f;
        float4 xv = *(const float4*)(g_xres + (size_t)n * DD + lane * 4);
#pragma unroll
        for (int k = 0; k < KK; k++) {
            float mk = __shfl_sync(0xffffffffu, m, k);
            if (mk != 0.f) {
                float4* a = (float4*)(acc + k * DD + lane * 4);
                float4 v = *a;
                v.x += xv.x; v.y += xv.y; v.z += xv.z; v.w += xv.w;
                *a = v;
            }
        }
        cnt += m;
    }
    if (lane < KK) scnt[wib][lane] = cnt;
    __syncthreads();

    float* outp = g_part + (size_t)blockIdx.x * KK * DD;
    for (int i = threadIdx.x; i < KK * DD; i += blockDim.x) {
        float v = 0.f;
#pragma unroll
        for (int w = 0; w < 8; w++) v += sacc[w][i];
        outp[i] = v;
    }
    if (threadIdx.x < KK) {
        float c = 0.f;
#pragma unroll
        for (int w = 0; w < 8; w++) c += scnt[w][threadIdx.x];
        g_cntpart[blockIdx.x * KK + threadIdx.x] = c;
    }
}

// ---------------------------------------------------------------------------
// Kernel 3b: reduce partials -> g_psum, g_pcnt
// ---------------------------------------------------------------------------
__global__ void reduce_kernel() {
    int tid = blockIdx.x * blockDim.x + threadIdx.x;
    int stride = gridDim.x * blockDim.x;
    for (int i = tid; i < BB * KK * DD; i += stride) {
        int b = i / (KK * DD);
        int j = i % (KK * DD);
        float v = 0.f;
#pragma unroll
        for (int s = 0; s < PS; s++) v += g_part[(size_t)(b * PS + s) * KK * DD + j];
        g_psum[i] = v;
    }
    for (int i = tid; i < BB * KK; i += stride) {
        int b = i / KK;
        int k = i % KK;
        float c = 0.f;
#pragma unroll
        for (int s = 0; s < PS; s++) c += g_cntpart[(b * PS + s) * KK + k];
        g_pcnt[i] = c;
    }
}

// ---------------------------------------------------------------------------
// Kernel 4: pocket_emb = (psum/(cnt+1e-9)) @ Wv + bv. Warp per row (512 rows).
// ---------------------------------------------------------------------------
__global__ void pemb_kernel(const float* __restrict__ Wv, const float* __restrict__ bv) {
    const int lane = threadIdx.x & 31;
    const int r = blockIdx.x * (blockDim.x >> 5) + (threadIdx.x >> 5);
    if (r >= BB * KK) return;
    const float rinv = 1.f / (g_pcnt[r] + 1e-9f);
    const int c0 = lane * 4;
    float4 acc = *(const float4*)(bv + c0);
#pragma unroll 8
    for (int d = 0; d < DD; d++) {
        float a = g_psum[r * DD + d] * rinv;
        float4 w = __ldg((const float4*)(Wv + d * DD + c0));
        acc.x += a * w.x; acc.y += a * w.y; acc.z += a * w.z; acc.w += a * w.w;
    }
    *(float4*)(g_pemb + r * DD + c0) = acc;
}

// ---------------------------------------------------------------------------
// Kernel 5: residual pocket feedback + LayerNorm + ReLU. Warp per node.
// ---------------------------------------------------------------------------
__global__ void final_kernel(const float* __restrict__ mask, const int* __restrict__ batch,
                             const float* __restrict__ gamma, const float* __restrict__ beta,
                             float* __restrict__ out) {
    const int lane = threadIdx.x & 31;
    const int gw = blockIdx.x * (blockDim.x >> 5) + (threadIdx.x >> 5);
    const int tw = gridDim.x * (blockDim.x >> 5);
    const int c0 = lane * 4;
    const float4 gm = *(const float4*)(gamma + c0);
    const float4 bt = *(const float4*)(beta + c0);

    for (int n = gw; n < NN; n += tw) {
        int g = batch[n];
        float m = (lane < KK) ? mask[(size_t)n * KK + lane] : 0.f;
        float4 v = *(const float4*)(g_xres + (size_t)n * DD + c0);
        const float* pe = g_pemb + (size_t)g * KK * DD;
#pragma unroll
        for (int k = 0; k < KK; k++) {
            float mk = __shfl_sync(0xffffffffu, m, k);
            if (mk != 0.f) {
                float4 p = __ldg((const float4*)(pe + k * DD + c0));
                v.x += p.x; v.y += p.y; v.z += p.z; v.w += p.w;
            }
        }
        float s = v.x + v.y + v.z + v.w;
#pragma unroll
        for (int off = 16; off; off >>= 1) s += __shfl_xor_sync(0xffffffffu, s, off);
        float mu = s * (1.f / 128.f);
        float dx = v.x - mu, dy = v.y - mu, dz = v.z - mu, dw = v.w - mu;
        float sq = dx * dx + dy * dy + dz * dz + dw * dw;
#pragma unroll
        for (int off = 16; off; off >>= 1) sq += __shfl_xor_sync(0xffffffffu, sq, off);
        float rstd = rsqrtf(sq * (1.f / 128.f) + 1e-5f);
        float4 y;
        y.x = fmaxf(dx * rstd * gm.x + bt.x, 0.f);
        y.y = fmaxf(dy * rstd * gm.y + bt.y, 0.f);
        y.z = fmaxf(dz * rstd * gm.z + bt.z, 0.f);
        y.w = fmaxf(dw * rstd * gm.w + bt.w, 0.f);
        *(float4*)(out + (size_t)n * DD + c0) = y;
    }
}

// ---------------------------------------------------------------------------
extern "C" void kernel_launch(void* const* d_in, const int* in_sizes, int n_in,
                              void* d_out, int out_size) {
    const float* x     = (const float*)d_in[0];
    const int*   ei    = (const int*)d_in[1];
    const float* ea    = (const float*)d_in[2];
    const float* pmask = (const float*)d_in[3];
    const int*   batch = (const int*)d_in[4];
    const float* We    = (const float*)d_in[5];
    const float* be    = (const float*)d_in[6];
    const float* W1    = (const float*)d_in[7];
    const float* b1    = (const float*)d_in[8];
    const float* W2    = (const float*)d_in[9];
    const float* b2    = (const float*)d_in[10];
    const float* eps   = (const float*)d_in[11];
    const float* gamma = (const float*)d_in[12];
    const float* beta  = (const float*)d_in[13];
    const float* Wv    = (const float*)d_in[14];
    const float* bv    = (const float*)d_in[15];
    float* out = (float*)d_out;

    const int MLP_SMEM = (16384 + TM * DD) * 4;   // 98304 bytes
    cudaFuncSetAttribute(mlp1_kernel, cudaFuncAttributeMaxDynamicSharedMemorySize, MLP_SMEM);
    cudaFuncSetAttribute(mlp2_kernel, cudaFuncAttributeMaxDynamicSharedMemorySize, MLP_SMEM);

    init_kernel<<<2048, 256>>>(x, eps);
    bounds_kernel<<<(NN + 255) / 256, 256>>>(batch);
    edge_kernel<<<4096, 256>>>(x, ei, ea, We, be);
    mlp1_kernel<<<(NN + TM - 1) / TM, 256, MLP_SMEM>>>(W1, b1);
    mlp2_kernel<<<(NN + TM - 1) / TM, 256, MLP_SMEM>>>(W2, b2);
    pool_kernel<<<BB * PS, 256>>>(pmask);
    reduce_kernel<<<64, 256>>>();
    pemb_kernel<<<(BB * KK + 7) / 8, 256>>>(Wv, bv);
    final_kernel<<<2048, 256>>>(pmask, batch, gamma, beta, out);
}